// round 7
// baseline (speedup 1.0000x reference)
#include <cuda_runtime.h>

// Problem constants (GNNLayer_64269890617631): x[B,N], edges E
#define BB 64
#define NN 20000
#define EE 1280000

// Scratch (all __device__ globals — no allocation allowed)
__device__ float  g_xt[(size_t)NN * BB];    // transposed features [N][B]
__device__ float  g_acc[(size_t)NN * BB];   // accumulator [N][B]
__device__ float2 g_pay[EE];                // CSR payload: {coeff, bitcast(src)}
__device__ int    g_count[NN + 1];          // per-dst edge counts
__device__ int    g_rowptr[NN + 1];         // CSR row pointers
__device__ int    g_ofs[NN];                // running offsets for scatter

// ───────────────────────────────────────────────────────────────────────────
// Kernel 1: transpose x [B,N] -> xt [N,B] (float4 both phases), zero counts.
#define PTILE 128
__global__ void prep_kernel(const float* __restrict__ x, int n_nodes) {
    __shared__ float tile[BB][PTILE + 4];
    const int nbase = blockIdx.x * PTILE;
    const int tid = threadIdx.x;  // 256 threads

    // zero histogram counters (grid covers N+1)
    const int gz = blockIdx.x * blockDim.x + tid;
    if (gz <= n_nodes) g_count[gz] = 0;

    // phase 1: coalesced float4 loads along N
    for (int idx = tid; idx < BB * (PTILE / 4); idx += 256) {
        const int i  = idx / (PTILE / 4);
        const int n4 = idx % (PTILE / 4);
        const int gn = nbase + n4 * 4;
        if (gn + 3 < n_nodes) {
            const float4 v = *(const float4*)(x + (size_t)i * n_nodes + gn);
            *(float4*)&tile[i][n4 * 4] = v;
        } else {
            for (int j = 0; j < 4; j++)
                tile[i][n4 * 4 + j] =
                    (gn + j < n_nodes) ? x[(size_t)i * n_nodes + gn + j] : 0.0f;
        }
    }
    __syncthreads();
    // phase 2: coalesced float4 stores along B
    for (int idx = tid; idx < PTILE * (BB / 4); idx += 256) {
        const int n  = idx / (BB / 4);
        const int i4 = idx % (BB / 4);
        const int gn = nbase + n;
        if (gn < n_nodes) {
            float4 v;
            v.x = tile[i4 * 4 + 0][n];
            v.y = tile[i4 * 4 + 1][n];
            v.z = tile[i4 * 4 + 2][n];
            v.w = tile[i4 * 4 + 3][n];
            ((float4*)g_xt)[(size_t)gn * (BB / 4) + i4] = v;
        }
    }
}

// ───────────────────────────────────────────────────────────────────────────
// Kernel 2: histogram of dst (4 edges per thread, spread-address atomics)
__global__ void hist_kernel(const int* __restrict__ dst, int n_edges) {
    const int e = (blockIdx.x * blockDim.x + threadIdx.x) * 4;
    if (e + 3 < n_edges) {
        const int4 d = *(const int4*)(dst + e);
        atomicAdd(&g_count[d.x], 1);
        atomicAdd(&g_count[d.y], 1);
        atomicAdd(&g_count[d.z], 1);
        atomicAdd(&g_count[d.w], 1);
    } else if (e < n_edges) {
        for (int j = e; j < n_edges; j++) atomicAdd(&g_count[dst[j]], 1);
    }
}

// ───────────────────────────────────────────────────────────────────────────
// Kernel 3: single-block exclusive scan of counts -> rowptr (+ofs copy)
#define SCAN_T 1024
__global__ void scan_kernel(int n) {
    __shared__ int warp_sums[32];
    const int tid = threadIdx.x;
    const int chunk = (n + SCAN_T - 1) / SCAN_T;
    const int beg = tid * chunk;
    const int end = min(beg + chunk, n);

    int s = 0;
    for (int i = beg; i < end; i++) s += g_count[i];

    const int lane = tid & 31, wid = tid >> 5;
    int v = s;
    #pragma unroll
    for (int off = 1; off < 32; off <<= 1) {
        const int t = __shfl_up_sync(0xFFFFFFFFu, v, off);
        if (lane >= off) v += t;
    }
    if (lane == 31) warp_sums[wid] = v;
    __syncthreads();
    if (wid == 0) {
        int wv = warp_sums[lane];
        #pragma unroll
        for (int off = 1; off < 32; off <<= 1) {
            const int t = __shfl_up_sync(0xFFFFFFFFu, wv, off);
            if (lane >= off) wv += t;
        }
        warp_sums[lane] = wv;
    }
    __syncthreads();

    int run = (v - s) + (wid > 0 ? warp_sums[wid - 1] : 0);  // exclusive prefix
    for (int i = beg; i < end; i++) {
        g_rowptr[i] = run;
        g_ofs[i] = run;
        run += g_count[i];
    }
    if (tid == SCAN_T - 1) g_rowptr[n] = run;
}

// ───────────────────────────────────────────────────────────────────────────
// Kernel 4: scatter edges into CSR slots (payload = {adj*w, src})
__global__ void scatter_kernel(const float* __restrict__ adj,
                               const float* __restrict__ w,
                               const int* __restrict__ src,
                               const int* __restrict__ dst,
                               int n_edges) {
    const int e = (blockIdx.x * blockDim.x + threadIdx.x) * 4;
    if (e + 3 < n_edges) {
        const float4 a  = *(const float4*)(adj + e);
        const float4 ww = *(const float4*)(w + e);
        const int4   s  = *(const int4*)(src + e);
        const int4   d  = *(const int4*)(dst + e);
        int p;
        p = atomicAdd(&g_ofs[d.x], 1); g_pay[p] = make_float2(a.x * ww.x, __int_as_float(s.x));
        p = atomicAdd(&g_ofs[d.y], 1); g_pay[p] = make_float2(a.y * ww.y, __int_as_float(s.y));
        p = atomicAdd(&g_ofs[d.z], 1); g_pay[p] = make_float2(a.z * ww.z, __int_as_float(s.z));
        p = atomicAdd(&g_ofs[d.w], 1); g_pay[p] = make_float2(a.w * ww.w, __int_as_float(s.w));
    } else if (e < n_edges) {
        for (int j = e; j < n_edges; j++) {
            const int p = atomicAdd(&g_ofs[dst[j]], 1);
            g_pay[p] = make_float2(adj[j] * w[j], __int_as_float(src[j]));
        }
    }
}

// ───────────────────────────────────────────────────────────────────────────
// Kernel 5: atomic-free aggregation. 16 lanes per dst node, float4 each;
// accumulator lives in registers, acc written ONCE per node.
__global__ void agg_kernel(int n_nodes) {
    const int g = (blockIdx.x * blockDim.x + threadIdx.x) >> 4;
    const int l = threadIdx.x & 15;
    if (g >= n_nodes) return;

    int k = g_rowptr[g];
    const int end = g_rowptr[g + 1];
    const float4* __restrict__ xt4 = (const float4*)g_xt;

    float4 a = make_float4(0.f, 0.f, 0.f, 0.f);
    // unroll 2 for MLP on the L2 gathers
    for (; k + 1 < end; k += 2) {
        const float2 p0 = __ldg(&g_pay[k]);
        const float2 p1 = __ldg(&g_pay[k + 1]);
        const float4 v0 = __ldg(&xt4[(size_t)__float_as_int(p0.y) * (BB / 4) + l]);
        const float4 v1 = __ldg(&xt4[(size_t)__float_as_int(p1.y) * (BB / 4) + l]);
        a.x += p0.x * v0.x; a.y += p0.x * v0.y; a.z += p0.x * v0.z; a.w += p0.x * v0.w;
        a.x += p1.x * v1.x; a.y += p1.x * v1.y; a.z += p1.x * v1.z; a.w += p1.x * v1.w;
    }
    if (k < end) {
        const float2 p = __ldg(&g_pay[k]);
        const float4 v = __ldg(&xt4[(size_t)__float_as_int(p.y) * (BB / 4) + l]);
        a.x += p.x * v.x; a.y += p.x * v.y; a.z += p.x * v.z; a.w += p.x * v.w;
    }
    ((float4*)g_acc)[(size_t)g * (BB / 4) + l] = a;
}

// ───────────────────────────────────────────────────────────────────────────
// Kernel 6: out[i][n] = relu(acc[n][i] * (x[0][n]*self_w[n]) + b[n])
#define FTILE 32
__global__ void final_kernel(const float* __restrict__ x,
                             const float* __restrict__ self_w,
                             const float* __restrict__ b,
                             float* __restrict__ out,
                             int n_nodes) {
    __shared__ float tile[FTILE][BB + 1];
    __shared__ float sl[FTILE];
    __shared__ float bias[FTILE];
    const int nbase = blockIdx.x * FTILE;
    const int tid = threadIdx.x;  // 256 threads

    if (tid < FTILE) {
        const int gn = nbase + tid;
        if (gn < n_nodes) {
            sl[tid] = x[gn] * self_w[gn];  // x row 0 (faithful quirk)
            bias[tid] = b[gn];
        }
    }
    for (int idx = tid; idx < FTILE * BB; idx += 256) {
        const int n = idx / BB;
        const int i = idx % BB;
        const int gn = nbase + n;
        if (gn < n_nodes) tile[n][i] = g_acc[(size_t)gn * BB + i];
    }
    __syncthreads();
    for (int idx = tid; idx < BB * FTILE; idx += 256) {
        const int i = idx / FTILE;
        const int n = idx % FTILE;
        const int gn = nbase + n;
        if (gn < n_nodes) {
            const float v = tile[n][i] * sl[n] + bias[n];
            out[(size_t)i * n_nodes + gn] = fmaxf(v, 0.0f);
        }
    }
}

// ───────────────────────────────────────────────────────────────────────────
extern "C" void kernel_launch(void* const* d_in, const int* in_sizes, int n_in,
                              void* d_out, int out_size) {
    // metadata order: x, adj_values, w, self_w, b, src, dst
    const float* x      = (const float*)d_in[0];
    const float* adj    = (const float*)d_in[1];
    const float* w      = (const float*)d_in[2];
    const float* self_w = (const float*)d_in[3];
    const float* b      = (const float*)d_in[4];
    const int*   src    = (const int*)d_in[5];
    const int*   dst    = (const int*)d_in[6];
    float* out = (float*)d_out;

    const int n_nodes = in_sizes[3];   // N from self_w
    const int n_edges = in_sizes[1];   // E from adj_values

    const int prep_blocks = (n_nodes + PTILE - 1) / PTILE;
    prep_kernel<<<prep_blocks, 256>>>(x, n_nodes);

    const int e4_blocks = ((n_edges + 3) / 4 + 255) / 256;
    hist_kernel<<<e4_blocks, 256>>>(dst, n_edges);

    scan_kernel<<<1, SCAN_T>>>(n_nodes);

    scatter_kernel<<<e4_blocks, 256>>>(adj, w, src, dst, n_edges);

    const int agg_blocks = (n_nodes * 16 + 255) / 256;
    agg_kernel<<<agg_blocks, 256>>>(n_nodes);

    const int fin_blocks = (n_nodes + FTILE - 1) / FTILE;
    final_kernel<<<fin_blocks, 256>>>(x, self_w, b, out, n_nodes);
}